// round 14
// baseline (speedup 1.0000x reference)
#include <cuda_runtime.h>
#include <cuda_bf16.h>
#include <cstdint>
#include <cstddef>

// Problem constants
#define BB 2
#define SS 2048
#define NH 8
#define DD 64
#define HID 512
#define NROWS (BB * SS)           // 4096
#define OUT_ELEMS (BB * SS * HID) // 2097152
#define NBH (BB * NH)             // 16
#define NKT (SS / 128)            // 16 k-tiles per row
#define KSPLIT 8

typedef unsigned long long u64t;

// ---------------- scratch (device globals; no allocation allowed) ----------------
__device__ float g_qh[NROWS * HID];
__device__ float g_kh[NROWS * HID];
__device__ float g_vh[NROWS * HID];
__device__ float g_ctx[KSPLIT][NROWS * HID];
__device__ float g_part[NBH * SS * NKT]; // per (row, ktile): tile sum of exp(logit)
__device__ float g_inv[NBH * SS];        // per row: 1 / sum exp

// ---------------- packed f32x2 helpers (sm_100+ base PTX feature) ----------------
__device__ __forceinline__ u64t pk2(float x, float y) {
    u64t r;
    asm("mov.b64 %0, {%1, %2};" : "=l"(r) : "f"(x), "f"(y));
    return r;
}
__device__ __forceinline__ void fma2(u64t& d, u64t a, u64t b) {
    asm("fma.rn.f32x2 %0, %1, %2, %0;" : "+l"(d) : "l"(a), "l"(b));
}
__device__ __forceinline__ float2 up2(u64t v) {
    float2 r;
    asm("mov.b64 {%0, %1}, %2;" : "=f"(r.x), "=f"(r.y) : "l"(v));
    return r;
}

// Fast exp on the FMA pipe. exp(x) = 2^(x*log2e). Max rel err ~1.3e-6.
// Clamped at 2^-126 so -1e9 inputs underflow to ~0. Logits are bounded
// (|logit| <~ 15) so no overflow without max-shifting.
__device__ __forceinline__ float fexp(float x) {
    float t = x * 1.4426950408889634f;
    t = fmaxf(t, -126.0f);
    float nf = floorf(t);
    float f = t - nf;
    float p = 1.5252733e-5f;
    p = fmaf(p, f, 1.5403530e-4f);
    p = fmaf(p, f, 1.3333558e-3f);
    p = fmaf(p, f, 9.6181291e-3f);
    p = fmaf(p, f, 5.5504109e-2f);
    p = fmaf(p, f, 2.4022651e-1f);
    p = fmaf(p, f, 6.9314718e-1f);
    p = fmaf(p, f, 1.0f);
    float s = __int_as_float(((int)nf + 127) << 23);
    return s * p;
}

// =====================================================================
// Kernel 1: fused QKV projection, register-prefetch pipelined, f32x2 FMA.
// =====================================================================
__global__ __launch_bounds__(256) void qkv_proj_kernel(
    const float* __restrict__ q, const float* __restrict__ k, const float* __restrict__ v,
    const float* __restrict__ Wq, const float* __restrict__ Wk, const float* __restrict__ Wv,
    const float* __restrict__ bq, const float* __restrict__ bk, const float* __restrict__ bv,
    float* __restrict__ qh, float* __restrict__ kh, float* __restrict__ vh) {
    __shared__ __align__(16) float sX[16][132];
    __shared__ __align__(16) float sW[16][132];

    const int z = blockIdx.z;
    const float* X = (z == 0) ? q : (z == 1) ? k : v;
    const float* W = (z == 0) ? Wq : (z == 1) ? Wk : Wv;
    const float* bias = (z == 0) ? bq : (z == 1) ? bk : bv;
    float* Y = (z == 0) ? qh : (z == 1) ? kh : vh;

    const int t = threadIdx.x;
    const int tx = t & 15, ty = t >> 4;
    const int row0 = blockIdx.y * 128;
    const int col0 = blockIdx.x * 128;

    const int lr = t >> 1;
    const int lc = (t & 1) * 8;
    const int wk = t >> 4;
    const int wc = (t & 15) * 8;

    u64t acc2[8][4] = {};
    float4 x0, x1, w0, w1;

    {
        size_t xo = (size_t)(row0 + lr) * HID + lc;
        x0 = *(const float4*)&X[xo];
        x1 = *(const float4*)&X[xo + 4];
        w0 = *(const float4*)&W[(size_t)wk * HID + col0 + wc];
        w1 = *(const float4*)&W[(size_t)wk * HID + col0 + wc + 4];
    }

    for (int kt = 0; kt < HID; kt += 16) {
        __syncthreads();
        sX[lc + 0][lr] = x0.x; sX[lc + 1][lr] = x0.y; sX[lc + 2][lr] = x0.z; sX[lc + 3][lr] = x0.w;
        sX[lc + 4][lr] = x1.x; sX[lc + 5][lr] = x1.y; sX[lc + 6][lr] = x1.z; sX[lc + 7][lr] = x1.w;
        *(float4*)&sW[wk][wc] = w0;
        *(float4*)&sW[wk][wc + 4] = w1;
        __syncthreads();

        int kn = kt + 16;
        if (kn < HID) {
            size_t xo = (size_t)(row0 + lr) * HID + kn + lc;
            x0 = *(const float4*)&X[xo];
            x1 = *(const float4*)&X[xo + 4];
            w0 = *(const float4*)&W[(size_t)(kn + wk) * HID + col0 + wc];
            w1 = *(const float4*)&W[(size_t)(kn + wk) * HID + col0 + wc + 4];
        }

#pragma unroll
        for (int kk = 0; kk < 16; kk++) {
            float4 a0 = *(float4*)&sX[kk][ty * 4];
            float4 a1 = *(float4*)&sX[kk][64 + ty * 4];
            ulonglong2 bA = *(ulonglong2*)&sW[kk][tx * 4];
            ulonglong2 bB = *(ulonglong2*)&sW[kk][64 + tx * 4];
            u64t b2[4] = {bA.x, bA.y, bB.x, bB.y};
            float a[8] = {a0.x, a0.y, a0.z, a0.w, a1.x, a1.y, a1.z, a1.w};
#pragma unroll
            for (int i = 0; i < 8; i++) {
                u64t a2 = pk2(a[i], a[i]);
#pragma unroll
                for (int p = 0; p < 4; p++)
                    fma2(acc2[i][p], a2, b2[p]);
            }
        }
    }

    float4 bv0 = *(const float4*)&bias[col0 + tx * 4];
    float4 bv1 = *(const float4*)&bias[col0 + 64 + tx * 4];
#pragma unroll
    for (int i = 0; i < 8; i++) {
        int rr = (i < 4) ? (ty * 4 + i) : (64 + ty * 4 + (i - 4));
        size_t base = (size_t)(row0 + rr) * HID;
        float2 c0 = up2(acc2[i][0]), c1 = up2(acc2[i][1]);
        float2 c2 = up2(acc2[i][2]), c3 = up2(acc2[i][3]);
        float4 o0, o1;
        o0.x = c0.x + bv0.x; o0.y = c0.y + bv0.y;
        o0.z = c1.x + bv0.z; o0.w = c1.y + bv0.w;
        o1.x = c2.x + bv1.x; o1.y = c2.y + bv1.y;
        o1.z = c3.x + bv1.z; o1.w = c3.y + bv1.w;
        *(float4*)&Y[base + col0 + tx * 4] = o0;
        *(float4*)&Y[base + col0 + 64 + tx * 4] = o1;
    }
}

// =====================================================================
// Kernel 2: fused logits + exp + tile row-sum, f32x2 mainloop, 3 CTAs/SM.
// =====================================================================
__global__ __launch_bounds__(256, 3) void logits_kernel(const float* __restrict__ qh,
                                                        const float* __restrict__ kh,
                                                        const float* __restrict__ bias,
                                                        const int* __restrict__ mask,
                                                        float* __restrict__ L,
                                                        float* __restrict__ part) {
    extern __shared__ float sm[];
    float* sQ = sm;            // [64][132] transposed [d][row]
    float* sK = sm + 64 * 132; // [64][132] transposed [d][col]

    const int t = threadIdx.x;
    const int tx = t & 15, ty = t >> 4;
    const int kt = blockIdx.x * 128;
    const int ktile = blockIdx.x;
    const int qt = blockIdx.y * 128;
    const int bh = blockIdx.z;
    const int b = bh >> 3, h = bh & 7;

    const float* Qb = qh + (size_t)b * SS * HID + h * DD;
    const float* Kb = kh + (size_t)b * SS * HID + h * DD;

#pragma unroll
    for (int i = 0; i < 8; i++) {
        int f4i = t + 256 * i;
        int r = f4i >> 4;
        int d4 = (f4i & 15) * 4;
        float4 xq = *(const float4*)&Qb[(size_t)(qt + r) * HID + d4];
        sQ[(d4 + 0) * 132 + r] = xq.x; sQ[(d4 + 1) * 132 + r] = xq.y;
        sQ[(d4 + 2) * 132 + r] = xq.z; sQ[(d4 + 3) * 132 + r] = xq.w;
        float4 xk = *(const float4*)&Kb[(size_t)(kt + r) * HID + d4];
        sK[(d4 + 0) * 132 + r] = xk.x; sK[(d4 + 1) * 132 + r] = xk.y;
        sK[(d4 + 2) * 132 + r] = xk.z; sK[(d4 + 3) * 132 + r] = xk.w;
    }
    __syncthreads();

    u64t acc2[8][4] = {}; // [row i][col pair p]
#pragma unroll
    for (int d = 0; d < 64; d++) {
        float4 a0 = *(float4*)&sQ[d * 132 + ty * 4];
        float4 a1 = *(float4*)&sQ[d * 132 + 64 + ty * 4];
        ulonglong2 bA = *(ulonglong2*)&sK[d * 132 + tx * 4];
        ulonglong2 bB = *(ulonglong2*)&sK[d * 132 + 64 + tx * 4];
        u64t b2[4] = {bA.x, bA.y, bB.x, bB.y};
        float a[8] = {a0.x, a0.y, a0.z, a0.w, a1.x, a1.y, a1.z, a1.w};
#pragma unroll
        for (int i = 0; i < 8; i++) {
            u64t a2 = pk2(a[i], a[i]);
#pragma unroll
            for (int p = 0; p < 4; p++)
                fma2(acc2[i][p], a2, b2[p]);
        }
    }

    const float scale = 0.125f;
#pragma unroll
    for (int i = 0; i < 8; i++) {
        int rr = (i < 4) ? (ty * 4 + i) : (64 + ty * 4 + (i - 4));
        int qr = qt + rr;
        size_t boff = ((size_t)bh * SS + qr) * SS + kt;
        size_t moff = ((size_t)b * SS + qr) * SS + kt;
        float2 c0 = up2(acc2[i][0]), c1 = up2(acc2[i][1]);
        float2 c2 = up2(acc2[i][2]), c3 = up2(acc2[i][3]);
        float ac[8] = {c0.x, c0.y, c1.x, c1.y, c2.x, c2.y, c3.x, c3.y};
        float e[8]; float s = 0.f;
#pragma unroll
        for (int g = 0; g < 2; g++) {
            int c = g * 64 + tx * 4;
            float4 bv = *(const float4*)&bias[boff + c];
            int4 mv = *(const int4*)&mask[moff + c];
            float v0 = mv.x ? -1e9f : fmaf(ac[4 * g + 0], scale, bv.x);
            float v1 = mv.y ? -1e9f : fmaf(ac[4 * g + 1], scale, bv.y);
            float v2 = mv.z ? -1e9f : fmaf(ac[4 * g + 2], scale, bv.z);
            float v3 = mv.w ? -1e9f : fmaf(ac[4 * g + 3], scale, bv.w);
            e[4 * g + 0] = fexp(v0); e[4 * g + 1] = fexp(v1);
            e[4 * g + 2] = fexp(v2); e[4 * g + 3] = fexp(v3);
            s += e[4 * g + 0] + e[4 * g + 1] + e[4 * g + 2] + e[4 * g + 3];
        }
#pragma unroll
        for (int off = 8; off >= 1; off >>= 1)
            s += __shfl_xor_sync(0xFFFFFFFFu, s, off);

        float4 o0 = {e[0], e[1], e[2], e[3]};
        float4 o1 = {e[4], e[5], e[6], e[7]};
        *(float4*)&L[boff + tx * 4] = o0;
        *(float4*)&L[boff + 64 + tx * 4] = o1;
        if (tx == 0)
            part[((size_t)bh * SS + qr) * NKT + ktile] = s;
    }
}

// =====================================================================
// Kernel 3: per-row reduce of tile sums -> inv_l
// =====================================================================
__global__ __launch_bounds__(256) void reduce_kernel(const float* __restrict__ part,
                                                     float* __restrict__ inv) {
    int row = blockIdx.x * 256 + threadIdx.x; // < NBH*SS
    float l = 0.f;
#pragma unroll
    for (int j = 0; j < NKT; j++)
        l += part[(size_t)row * NKT + j];
    inv[row] = 1.0f / l;
}

// =====================================================================
// Kernel 4: P = E * inv_l (in-place) and ctx_partial = P @ V.
// BM=128, BN=64, BK=32, 256 threads, split-K=8, reg-prefetch, f32x2 FMA.
// =====================================================================
__global__ __launch_bounds__(256) void pv_kernel(float* __restrict__ P,
                                                 const float* __restrict__ vh,
                                                 const float* __restrict__ inv,
                                                 float* __restrict__ ctxbase) {
    __shared__ __align__(16) float sE[32 * 132]; // [k][row]
    __shared__ __align__(16) float sV[32 * 68];  // [k][col]
    __shared__ __align__(16) float sInv[128];

    const int t = threadIdx.x;
    const int tx = t & 15, ty = t >> 4;
    const int qt = blockIdx.x * 128;
    const int bh = blockIdx.y;
    const int ks = blockIdx.z;
    const int b = bh >> 3, h = bh & 7;

    float* dst = ctxbase + (size_t)ks * NROWS * HID;

    if (t < 128) sInv[t] = inv[(size_t)bh * SS + qt + t];

    u64t acc2[4][4] = {}; // [row pair p][col j]
    float* Pb = P + ((size_t)bh * SS + qt) * SS;
    const float* Vb = vh + (size_t)b * SS * HID + h * DD;

    const int er = t >> 3;          // base E row 0..31 (i adds 32*i)
    const int ec = (t & 7) * 4;     // E col-in-tile 0..28
    const int vr = t >> 4;          // base V k-row 0..15 (i adds 16*i)
    const int vc = (t & 15) * 4;    // V col 0..60

    const int kbeg = ks * (SS / KSPLIT);
    const int kend = kbeg + SS / KSPLIT;

    float4 eR[4], vR[2];
#pragma unroll
    for (int i = 0; i < 4; i++)
        eR[i] = *(const float4*)&Pb[(size_t)(er + 32 * i) * SS + kbeg + ec];
#pragma unroll
    for (int i = 0; i < 2; i++)
        vR[i] = *(const float4*)&Vb[(size_t)(kbeg + vr + 16 * i) * HID + vc];

    __syncthreads(); // sInv visible

    for (int k0 = kbeg; k0 < kend; k0 += 32) {
#pragma unroll
        for (int i = 0; i < 4; i++) {
            int r = er + 32 * i;
            float f = sInv[r];
            float4 pvv;
            pvv.x = eR[i].x * f; pvv.y = eR[i].y * f;
            pvv.z = eR[i].z * f; pvv.w = eR[i].w * f;
            *(float4*)&Pb[(size_t)r * SS + k0 + ec] = pvv;
            sE[(ec + 0) * 132 + r] = pvv.x;
            sE[(ec + 1) * 132 + r] = pvv.y;
            sE[(ec + 2) * 132 + r] = pvv.z;
            sE[(ec + 3) * 132 + r] = pvv.w;
        }
#pragma unroll
        for (int i = 0; i < 2; i++)
            *(float4*)&sV[(vr + 16 * i) * 68 + vc] = vR[i];
        __syncthreads();

        int kn = k0 + 32;
        if (kn < kend) {
#pragma unroll
            for (int i = 0; i < 4; i++)
                eR[i] = *(const float4*)&Pb[(size_t)(er + 32 * i) * SS + kn + ec];
#pragma unroll
            for (int i = 0; i < 2; i++)
                vR[i] = *(const float4*)&Vb[(size_t)(kn + vr + 16 * i) * HID + vc];
        }

#pragma unroll
        for (int kk = 0; kk < 32; kk++) {
            ulonglong2 aA = *(ulonglong2*)&sE[kk * 132 + ty * 4];
            ulonglong2 aB = *(ulonglong2*)&sE[kk * 132 + 64 + ty * 4];
            float4 bv = *(float4*)&sV[kk * 68 + tx * 4];
            u64t a2[4] = {aA.x, aA.y, aB.x, aB.y};
            u64t b2[4] = {pk2(bv.x, bv.x), pk2(bv.y, bv.y),
                          pk2(bv.z, bv.z), pk2(bv.w, bv.w)};
#pragma unroll
            for (int p = 0; p < 4; p++)
#pragma unroll
                for (int j = 0; j < 4; j++)
                    fma2(acc2[p][j], a2[p], b2[j]);
        }
        __syncthreads();
    }

#pragma unroll
    for (int p = 0; p < 4; p++) {
        float2 c0 = up2(acc2[p][0]), c1 = up2(acc2[p][1]);
        float2 c2 = up2(acc2[p][2]), c3 = up2(acc2[p][3]);
        int r0 = (p < 2) ? (ty * 4 + 2 * p) : (64 + ty * 4 + 2 * (p - 2));
        size_t base0 = (size_t)(b * SS + qt + r0) * HID + h * DD + tx * 4;
        size_t base1 = (size_t)(b * SS + qt + r0 + 1) * HID + h * DD + tx * 4;
        float4 oLo = {c0.x, c1.x, c2.x, c3.x};
        float4 oHi = {c0.y, c1.y, c2.y, c3.y};
        *(float4*)&dst[base0] = oLo;
        *(float4*)&dst[base1] = oHi;
    }
}

// =====================================================================
// Kernel 5: output projection  Y = (sum of 8 ctx partials) @ W + b, f32x2.
// =====================================================================
__global__ __launch_bounds__(256) void out_proj_kernel(const float* __restrict__ Xb,
                                                       const float* __restrict__ W,
                                                       const float* __restrict__ bias,
                                                       float* __restrict__ Y) {
    __shared__ __align__(16) float sX[16][132];
    __shared__ __align__(16) float sW[16][132];

    const int t = threadIdx.x;
    const int tx = t & 15, ty = t >> 4;
    const int row0 = blockIdx.y * 128;
    const int col0 = blockIdx.x * 128;

    const int lr = t >> 1;
    const int lc = (t & 1) * 8;
    const int wk = t >> 4;
    const int wc = (t & 15) * 8;

    u64t acc2[8][4] = {};
    float4 x0, x1, w0, w1;

    auto loadX = [&](int kt, float4& a0, float4& a1) {
        size_t xo = (size_t)(row0 + lr) * HID + kt + lc;
        float4 s0 = *(const float4*)&Xb[xo];
        float4 s1 = *(const float4*)&Xb[xo + 4];
#pragma unroll
        for (int p = 1; p < KSPLIT; p++) {
            const float* Xp = Xb + (size_t)p * NROWS * HID;
            float4 y0 = *(const float4*)&Xp[xo];
            float4 y1 = *(const float4*)&Xp[xo + 4];
            s0.x += y0.x; s0.y += y0.y; s0.z += y0.z; s0.w += y0.w;
            s1.x += y1.x; s1.y += y1.y; s1.z += y1.z; s1.w += y1.w;
        }
        a0 = s0; a1 = s1;
    };

    loadX(0, x0, x1);
    w0 = *(const float4*)&W[(size_t)wk * HID + col0 + wc];
    w1 = *(const float4*)&W[(size_t)wk * HID + col0 + wc + 4];

    for (int kt = 0; kt < HID; kt += 16) {
        __syncthreads();
        sX[lc + 0][lr] = x0.x; sX[lc + 1][lr] = x0.y; sX[lc + 2][lr] = x0.z; sX[lc + 3][lr] = x0.w;
        sX[lc + 4][lr] = x1.x; sX[lc + 5][lr] = x1.y; sX[lc + 6][lr] = x1.z; sX[lc + 7][lr] = x1.w;
        *(float4*)&sW[wk][wc] = w0;
        *(float4*)&sW[wk][wc + 4] = w1;
        __syncthreads();

        int kn = kt + 16;
        if (kn < HID) {
            loadX(kn, x0, x1);
            w0 = *(const float4*)&W[(size_t)(kn + wk) * HID + col0 + wc];
            w1 = *(const float4*)&W[(size_t)(kn + wk) * HID + col0 + wc + 4];
        }

#pragma unroll
        for (int kk = 0; kk < 16; kk++) {
            float4 a0 = *(float4*)&sX[kk][ty * 4];
            float4 a1 = *(float4*)&sX[kk][64 + ty * 4];
            ulonglong2 bA = *(ulonglong2*)&sW[kk][tx * 4];
            ulonglong2 bB = *(ulonglong2*)&sW[kk][64 + tx * 4];
            u64t b2[4] = {bA.x, bA.y, bB.x, bB.y};
            float a[8] = {a0.x, a0.y, a0.z, a0.w, a1.x, a1.y, a1.z, a1.w};
#pragma unroll
            for (int i = 0; i < 8; i++) {
                u64t a2 = pk2(a[i], a[i]);
#pragma unroll
                for (int p = 0; p < 4; p++)
                    fma2(acc2[i][p], a2, b2[p]);
            }
        }
    }

    float4 bv0 = *(const float4*)&bias[col0 + tx * 4];
    float4 bv1 = *(const float4*)&bias[col0 + 64 + tx * 4];
#pragma unroll
    for (int i = 0; i < 8; i++) {
        int rr = (i < 4) ? (ty * 4 + i) : (64 + ty * 4 + (i - 4));
        size_t base = (size_t)(row0 + rr) * HID;
        float2 c0 = up2(acc2[i][0]), c1 = up2(acc2[i][1]);
        float2 c2 = up2(acc2[i][2]), c3 = up2(acc2[i][3]);
        float4 o0, o1;
        o0.x = c0.x + bv0.x; o0.y = c0.y + bv0.y;
        o0.z = c1.x + bv0.z; o0.w = c1.y + bv0.w;
        o1.x = c2.x + bv1.x; o1.y = c2.y + bv1.y;
        o1.z = c3.x + bv1.z; o1.w = c3.y + bv1.w;
        *(float4*)&Y[base + col0 + tx * 4] = o0;
        *(float4*)&Y[base + col0 + 64 + tx * 4] = o1;
    }
}

// =====================================================================
// Host launcher
// =====================================================================
extern "C" void kernel_launch(void* const* d_in, const int* in_sizes, int n_in,
                              void* d_out, int out_size) {
    const float* q = (const float*)d_in[0];
    const float* k = (const float*)d_in[1];
    const float* v = (const float*)d_in[2];
    const float* attn_bias = (const float*)d_in[3];
    const int* attn_mask = (const int*)d_in[4];
    const float* Wq = (const float*)d_in[5];
    const float* bq = (const float*)d_in[6];
    const float* Wk = (const float*)d_in[7];
    const float* bk = (const float*)d_in[8];
    const float* Wv = (const float*)d_in[9];
    const float* bv = (const float*)d_in[10];
    const float* Wo = (const float*)d_in[11];
    const float* bo = (const float*)d_in[12];

    float* out = (float*)d_out;
    float* scores = out + (size_t)OUT_ELEMS;

    float *qh, *kh, *vh, *ctx, *part, *inv;
    cudaGetSymbolAddress((void**)&qh, g_qh);
    cudaGetSymbolAddress((void**)&kh, g_kh);
    cudaGetSymbolAddress((void**)&vh, g_vh);
    cudaGetSymbolAddress((void**)&ctx, g_ctx);
    cudaGetSymbolAddress((void**)&part, g_part);
    cudaGetSymbolAddress((void**)&inv, g_inv);

    dim3 qg(HID / 128, NROWS / 128, 3); // (4, 32, 3)
    qkv_proj_kernel<<<qg, 256>>>(q, k, v, Wq, Wk, Wv, bq, bk, bv, qh, kh, vh);

    const int lsmem = 2 * 64 * 132 * (int)sizeof(float); // 67584
    cudaFuncSetAttribute(logits_kernel, cudaFuncAttributeMaxDynamicSharedMemorySize, lsmem);
    dim3 lg(SS / 128, SS / 128, NBH); // (16,16,16)
    logits_kernel<<<lg, 256, lsmem>>>(qh, kh, attn_bias, attn_mask, scores, part);

    reduce_kernel<<<(NBH * SS) / 256, 256>>>(part, inv);

    dim3 vg(SS / 128, NBH, KSPLIT); // (16,16,8)
    pv_kernel<<<vg, 256>>>(scores, vh, inv, ctx);

    dim3 pg(HID / 128, NROWS / 128); // (4, 32)
    out_proj_kernel<<<pg, 256>>>(ctx, Wo, bo, out);
}

// round 15
// speedup vs baseline: 1.0692x; 1.0692x over previous
#include <cuda_runtime.h>
#include <cuda_bf16.h>
#include <cstdint>
#include <cstddef>

// Problem constants
#define BB 2
#define SS 2048
#define NH 8
#define DD 64
#define HID 512
#define NROWS (BB * SS)           // 4096
#define OUT_ELEMS (BB * SS * HID) // 2097152
#define NBH (BB * NH)             // 16
#define LKT (SS / 64)             // 32 k-tiles per row (logits tile width 64)

typedef unsigned long long u64t;

// ---------------- scratch (device globals; no allocation allowed) ----------------
__device__ float g_qh[NROWS * HID];
__device__ float g_kh[NROWS * HID];
__device__ float g_vh[NROWS * HID];
__device__ float g_ctx0[NROWS * HID];
__device__ float g_ctx1[NROWS * HID];
__device__ float g_ctx2[NROWS * HID];
__device__ float g_ctx3[NROWS * HID];
__device__ float g_part[NBH * SS * LKT]; // per (row, ktile): tile sum of exp(logit)
__device__ float g_inv[NBH * SS];        // per row: 1 / sum exp

// ---------------- packed f32x2 helpers (sm_100+ base PTX feature) ----------------
__device__ __forceinline__ u64t pk2(float x, float y) {
    u64t r;
    asm("mov.b64 %0, {%1, %2};" : "=l"(r) : "f"(x), "f"(y));
    return r;
}
__device__ __forceinline__ void fma2(u64t& d, u64t a, u64t b) {
    asm("fma.rn.f32x2 %0, %1, %2, %0;" : "+l"(d) : "l"(a), "l"(b));
}
__device__ __forceinline__ float2 up2(u64t v) {
    float2 r;
    asm("mov.b64 {%0, %1}, %2;" : "=f"(r.x), "=f"(r.y) : "l"(v));
    return r;
}

// Fast exp on the FMA pipe. exp(x) = 2^(x*log2e). Max rel err ~1.3e-6.
// Clamped at 2^-126 so -1e9 inputs underflow to ~0. Logits are bounded
// (|logit| <~ 15) so no overflow without max-shifting.
__device__ __forceinline__ float fexp(float x) {
    float t = x * 1.4426950408889634f;
    t = fmaxf(t, -126.0f);
    float nf = floorf(t);
    float f = t - nf;
    float p = 1.5252733e-5f;
    p = fmaf(p, f, 1.5403530e-4f);
    p = fmaf(p, f, 1.3333558e-3f);
    p = fmaf(p, f, 9.6181291e-3f);
    p = fmaf(p, f, 5.5504109e-2f);
    p = fmaf(p, f, 2.4022651e-1f);
    p = fmaf(p, f, 6.9314718e-1f);
    p = fmaf(p, f, 1.0f);
    float s = __int_as_float(((int)nf + 127) << 23);
    return s * p;
}

// =====================================================================
// Kernel 1: fused QKV projection, register-prefetch pipelined, f32x2 FMA.
// =====================================================================
__global__ __launch_bounds__(256) void qkv_proj_kernel(
    const float* __restrict__ q, const float* __restrict__ k, const float* __restrict__ v,
    const float* __restrict__ Wq, const float* __restrict__ Wk, const float* __restrict__ Wv,
    const float* __restrict__ bq, const float* __restrict__ bk, const float* __restrict__ bv,
    float* __restrict__ qh, float* __restrict__ kh, float* __restrict__ vh) {
    __shared__ __align__(16) float sX[16][132];
    __shared__ __align__(16) float sW[16][132];

    const int z = blockIdx.z;
    const float* X = (z == 0) ? q : (z == 1) ? k : v;
    const float* W = (z == 0) ? Wq : (z == 1) ? Wk : Wv;
    const float* bias = (z == 0) ? bq : (z == 1) ? bk : bv;
    float* Y = (z == 0) ? qh : (z == 1) ? kh : vh;

    const int t = threadIdx.x;
    const int tx = t & 15, ty = t >> 4;
    const int row0 = blockIdx.y * 128;
    const int col0 = blockIdx.x * 128;

    const int lr = t >> 1;
    const int lc = (t & 1) * 8;
    const int wk = t >> 4;
    const int wc = (t & 15) * 8;

    u64t acc2[8][4] = {};
    float4 x0, x1, w0, w1;

    {
        size_t xo = (size_t)(row0 + lr) * HID + lc;
        x0 = *(const float4*)&X[xo];
        x1 = *(const float4*)&X[xo + 4];
        w0 = *(const float4*)&W[(size_t)wk * HID + col0 + wc];
        w1 = *(const float4*)&W[(size_t)wk * HID + col0 + wc + 4];
    }

    for (int kt = 0; kt < HID; kt += 16) {
        __syncthreads();
        sX[lc + 0][lr] = x0.x; sX[lc + 1][lr] = x0.y; sX[lc + 2][lr] = x0.z; sX[lc + 3][lr] = x0.w;
        sX[lc + 4][lr] = x1.x; sX[lc + 5][lr] = x1.y; sX[lc + 6][lr] = x1.z; sX[lc + 7][lr] = x1.w;
        *(float4*)&sW[wk][wc] = w0;
        *(float4*)&sW[wk][wc + 4] = w1;
        __syncthreads();

        int kn = kt + 16;
        if (kn < HID) { // issue next tile's loads under the FMA loop
            size_t xo = (size_t)(row0 + lr) * HID + kn + lc;
            x0 = *(const float4*)&X[xo];
            x1 = *(const float4*)&X[xo + 4];
            w0 = *(const float4*)&W[(size_t)(kn + wk) * HID + col0 + wc];
            w1 = *(const float4*)&W[(size_t)(kn + wk) * HID + col0 + wc + 4];
        }

#pragma unroll
        for (int kk = 0; kk < 16; kk++) {
            float4 a0 = *(float4*)&sX[kk][ty * 4];
            float4 a1 = *(float4*)&sX[kk][64 + ty * 4];
            ulonglong2 bA = *(ulonglong2*)&sW[kk][tx * 4];
            ulonglong2 bB = *(ulonglong2*)&sW[kk][64 + tx * 4];
            u64t b2[4] = {bA.x, bA.y, bB.x, bB.y};
            float a[8] = {a0.x, a0.y, a0.z, a0.w, a1.x, a1.y, a1.z, a1.w};
#pragma unroll
            for (int i = 0; i < 8; i++) {
                u64t a2 = pk2(a[i], a[i]);
#pragma unroll
                for (int p = 0; p < 4; p++)
                    fma2(acc2[i][p], a2, b2[p]);
            }
        }
    }

    float4 bv0 = *(const float4*)&bias[col0 + tx * 4];
    float4 bv1 = *(const float4*)&bias[col0 + 64 + tx * 4];
#pragma unroll
    for (int i = 0; i < 8; i++) {
        int rr = (i < 4) ? (ty * 4 + i) : (64 + ty * 4 + (i - 4));
        size_t base = (size_t)(row0 + rr) * HID;
        float2 c0 = up2(acc2[i][0]), c1 = up2(acc2[i][1]);
        float2 c2 = up2(acc2[i][2]), c3 = up2(acc2[i][3]);
        float4 o0, o1;
        o0.x = c0.x + bv0.x; o0.y = c0.y + bv0.y;
        o0.z = c1.x + bv0.z; o0.w = c1.y + bv0.w;
        o1.x = c2.x + bv1.x; o1.y = c2.y + bv1.y;
        o1.z = c3.x + bv1.z; o1.w = c3.y + bv1.w;
        *(float4*)&Y[base + col0 + tx * 4] = o0;
        *(float4*)&Y[base + col0 + 64 + tx * 4] = o1;
    }
}

// =====================================================================
// Kernel 2: fused logits + exp + tile row-sum, f32x2 mainloop.
// CTA tile 128q x 64k (half-width): acc regs halve -> 3 CTAs/SM natively.
// Thread tile: 8 rows x 4 cols. Grid (32, 16, 16).
// =====================================================================
__global__ __launch_bounds__(256) void logits_kernel(const float* __restrict__ qh,
                                                     const float* __restrict__ kh,
                                                     const float* __restrict__ bias,
                                                     const int* __restrict__ mask,
                                                     float* __restrict__ L,
                                                     float* __restrict__ part) {
    extern __shared__ float sm[];
    float* sQ = sm;            // [64][132] transposed [d][qrow]
    float* sK = sm + 64 * 132; // [64][68]  transposed [d][kcol]

    const int t = threadIdx.x;
    const int tx = t & 15, ty = t >> 4;
    const int kt = blockIdx.x * 64;
    const int ktile = blockIdx.x;
    const int qt = blockIdx.y * 128;
    const int bh = blockIdx.z;
    const int b = bh >> 3, h = bh & 7;

    const float* Qb = qh + (size_t)b * SS * HID + h * DD;
    const float* Kb = kh + (size_t)b * SS * HID + h * DD;

    // stage Q 128x64 (transposed)
#pragma unroll
    for (int i = 0; i < 8; i++) {
        int f4i = t + 256 * i;       // 0..2047
        int r = f4i >> 4;            // 0..127
        int d4 = (f4i & 15) * 4;     // 0..60
        float4 xq = *(const float4*)&Qb[(size_t)(qt + r) * HID + d4];
        sQ[(d4 + 0) * 132 + r] = xq.x; sQ[(d4 + 1) * 132 + r] = xq.y;
        sQ[(d4 + 2) * 132 + r] = xq.z; sQ[(d4 + 3) * 132 + r] = xq.w;
    }
    // stage K 64x64 (transposed)
#pragma unroll
    for (int i = 0; i < 4; i++) {
        int f4i = t + 256 * i;       // 0..1023
        int r = f4i >> 4;            // 0..63
        int d4 = (f4i & 15) * 4;     // 0..60
        float4 xk = *(const float4*)&Kb[(size_t)(kt + r) * HID + d4];
        sK[(d4 + 0) * 68 + r] = xk.x; sK[(d4 + 1) * 68 + r] = xk.y;
        sK[(d4 + 2) * 68 + r] = xk.z; sK[(d4 + 3) * 68 + r] = xk.w;
    }
    __syncthreads();

    u64t acc2[8][2] = {}; // [row i][col pair p] -> cols tx*4 + 2p + {0,1}
#pragma unroll
    for (int d = 0; d < 64; d++) {
        float4 a0 = *(float4*)&sQ[d * 132 + ty * 4];
        float4 a1 = *(float4*)&sQ[d * 132 + 64 + ty * 4];
        ulonglong2 bA = *(ulonglong2*)&sK[d * 68 + tx * 4];
        float a[8] = {a0.x, a0.y, a0.z, a0.w, a1.x, a1.y, a1.z, a1.w};
#pragma unroll
        for (int i = 0; i < 8; i++) {
            u64t a2 = pk2(a[i], a[i]);
            fma2(acc2[i][0], a2, bA.x);
            fma2(acc2[i][1], a2, bA.y);
        }
    }

    const float scale = 0.125f;
#pragma unroll
    for (int i = 0; i < 8; i++) {
        int rr = (i < 4) ? (ty * 4 + i) : (64 + ty * 4 + (i - 4));
        int qr = qt + rr;
        size_t boff = ((size_t)bh * SS + qr) * SS + kt;
        size_t moff = ((size_t)b * SS + qr) * SS + kt;
        float2 c0 = up2(acc2[i][0]), c1 = up2(acc2[i][1]);
        int c = tx * 4;
        float4 bv = *(const float4*)&bias[boff + c];
        int4 mv = *(const int4*)&mask[moff + c];
        float v0 = mv.x ? -1e9f : fmaf(c0.x, scale, bv.x);
        float v1 = mv.y ? -1e9f : fmaf(c0.y, scale, bv.y);
        float v2 = mv.z ? -1e9f : fmaf(c1.x, scale, bv.z);
        float v3 = mv.w ? -1e9f : fmaf(c1.y, scale, bv.w);
        float e0 = fexp(v0), e1 = fexp(v1), e2 = fexp(v2), e3 = fexp(v3);
        float s = (e0 + e1) + (e2 + e3);
#pragma unroll
        for (int off = 8; off >= 1; off >>= 1)
            s += __shfl_xor_sync(0xFFFFFFFFu, s, off);

        float4 o = {e0, e1, e2, e3};
        *(float4*)&L[boff + c] = o;
        if (tx == 0)
            part[((size_t)bh * SS + qr) * LKT + ktile] = s;
    }
}

// =====================================================================
// Kernel 3: per-row reduce of tile sums -> inv_l
// =====================================================================
__global__ __launch_bounds__(256) void reduce_kernel(const float* __restrict__ part,
                                                     float* __restrict__ inv) {
    int row = blockIdx.x * 256 + threadIdx.x; // < NBH*SS
    float l = 0.f;
#pragma unroll
    for (int j = 0; j < LKT; j++)
        l += part[(size_t)row * LKT + j];
    inv[row] = 1.0f / l;
}

// =====================================================================
// Kernel 4: P = E * inv_l (in-place) and ctx_partial = P @ V.
// BM=128, BN=64, BK=32, 256 threads, split-K=4, reg-prefetch, f32x2 FMA.
// (R13 version, unchanged.)
// =====================================================================
__global__ __launch_bounds__(256) void pv_kernel(float* __restrict__ P,
                                                 const float* __restrict__ vh,
                                                 const float* __restrict__ inv,
                                                 float* __restrict__ ctx0,
                                                 float* __restrict__ ctx1,
                                                 float* __restrict__ ctx2,
                                                 float* __restrict__ ctx3) {
    __shared__ __align__(16) float sE[32 * 132]; // [k][row]
    __shared__ __align__(16) float sV[32 * 68];  // [k][col]
    __shared__ __align__(16) float sInv[128];

    const int t = threadIdx.x;
    const int tx = t & 15, ty = t >> 4;
    const int qt = blockIdx.x * 128;
    const int bh = blockIdx.y;
    const int ks = blockIdx.z;
    const int b = bh >> 3, h = bh & 7;

    float* dst = (ks == 0) ? ctx0 : (ks == 1) ? ctx1 : (ks == 2) ? ctx2 : ctx3;

    if (t < 128) sInv[t] = inv[(size_t)bh * SS + qt + t];

    u64t acc2[4][4] = {}; // [row pair p][col j]
    float* Pb = P + ((size_t)bh * SS + qt) * SS;
    const float* Vb = vh + (size_t)b * SS * HID + h * DD;

    const int er = t >> 3;          // base E row 0..31 (i adds 32*i)
    const int ec = (t & 7) * 4;     // E col-in-tile 0..28
    const int vr = t >> 4;          // base V k-row 0..15 (i adds 16*i)
    const int vc = (t & 15) * 4;    // V col 0..60

    const int kbeg = ks * (SS / 4);
    const int kend = kbeg + SS / 4;

    float4 eR[4], vR[2];
#pragma unroll
    for (int i = 0; i < 4; i++)
        eR[i] = *(const float4*)&Pb[(size_t)(er + 32 * i) * SS + kbeg + ec];
#pragma unroll
    for (int i = 0; i < 2; i++)
        vR[i] = *(const float4*)&Vb[(size_t)(kbeg + vr + 16 * i) * HID + vc];

    __syncthreads(); // sInv visible

    for (int k0 = kbeg; k0 < kend; k0 += 32) {
#pragma unroll
        for (int i = 0; i < 4; i++) {
            int r = er + 32 * i;
            float f = sInv[r];
            float4 pvv;
            pvv.x = eR[i].x * f; pvv.y = eR[i].y * f;
            pvv.z = eR[i].z * f; pvv.w = eR[i].w * f;
            *(float4*)&Pb[(size_t)r * SS + k0 + ec] = pvv;
            sE[(ec + 0) * 132 + r] = pvv.x;
            sE[(ec + 1) * 132 + r] = pvv.y;
            sE[(ec + 2) * 132 + r] = pvv.z;
            sE[(ec + 3) * 132 + r] = pvv.w;
        }
#pragma unroll
        for (int i = 0; i < 2; i++)
            *(float4*)&sV[(vr + 16 * i) * 68 + vc] = vR[i];
        __syncthreads();

        int kn = k0 + 32;
        if (kn < kend) {
#pragma unroll
            for (int i = 0; i < 4; i++)
                eR[i] = *(const float4*)&Pb[(size_t)(er + 32 * i) * SS + kn + ec];
#pragma unroll
            for (int i = 0; i < 2; i++)
                vR[i] = *(const float4*)&Vb[(size_t)(kn + vr + 16 * i) * HID + vc];
        }

#pragma unroll
        for (int kk = 0; kk < 32; kk++) {
            ulonglong2 aA = *(ulonglong2*)&sE[kk * 132 + ty * 4];
            ulonglong2 aB = *(ulonglong2*)&sE[kk * 132 + 64 + ty * 4];
            float4 bv = *(float4*)&sV[kk * 68 + tx * 4];
            u64t a2[4] = {aA.x, aA.y, aB.x, aB.y};
            u64t b2[4] = {pk2(bv.x, bv.x), pk2(bv.y, bv.y),
                          pk2(bv.z, bv.z), pk2(bv.w, bv.w)};
#pragma unroll
            for (int p = 0; p < 4; p++)
#pragma unroll
                for (int j = 0; j < 4; j++)
                    fma2(acc2[p][j], a2[p], b2[j]);
        }
        __syncthreads();
    }

#pragma unroll
    for (int p = 0; p < 4; p++) {
        float2 c0 = up2(acc2[p][0]), c1 = up2(acc2[p][1]);
        float2 c2 = up2(acc2[p][2]), c3 = up2(acc2[p][3]);
        int r0 = (p < 2) ? (ty * 4 + 2 * p) : (64 + ty * 4 + 2 * (p - 2));
        size_t base0 = (size_t)(b * SS + qt + r0) * HID + h * DD + tx * 4;
        size_t base1 = (size_t)(b * SS + qt + r0 + 1) * HID + h * DD + tx * 4;
        float4 oLo = {c0.x, c1.x, c2.x, c3.x};
        float4 oHi = {c0.y, c1.y, c2.y, c3.y};
        *(float4*)&dst[base0] = oLo;
        *(float4*)&dst[base1] = oHi;
    }
}

// =====================================================================
// Kernel 5: output projection  Y = (X0+X1+X2+X3) @ W + b, f32x2 FMA.
// (R13 version, unchanged.)
// =====================================================================
__global__ __launch_bounds__(256) void out_proj_kernel(const float* __restrict__ X0,
                                                       const float* __restrict__ X1,
                                                       const float* __restrict__ X2,
                                                       const float* __restrict__ X3,
                                                       const float* __restrict__ W,
                                                       const float* __restrict__ bias,
                                                       float* __restrict__ Y) {
    __shared__ __align__(16) float sX[16][132];
    __shared__ __align__(16) float sW[16][132];

    const int t = threadIdx.x;
    const int tx = t & 15, ty = t >> 4;
    const int row0 = blockIdx.y * 128;
    const int col0 = blockIdx.x * 128;

    const int lr = t >> 1;
    const int lc = (t & 1) * 8;
    const int wk = t >> 4;
    const int wc = (t & 15) * 8;

    u64t acc2[8][4] = {};
    float4 x0, x1, w0, w1;

    auto loadX = [&](int kt, float4& a0, float4& a1) {
        size_t xo = (size_t)(row0 + lr) * HID + kt + lc;
        float4 p0 = *(const float4*)&X0[xo];
        float4 p1 = *(const float4*)&X0[xo + 4];
        float4 q0 = *(const float4*)&X1[xo];
        float4 q1 = *(const float4*)&X1[xo + 4];
        float4 r0 = *(const float4*)&X2[xo];
        float4 r1 = *(const float4*)&X2[xo + 4];
        float4 s0 = *(const float4*)&X3[xo];
        float4 s1 = *(const float4*)&X3[xo + 4];
        a0.x = (p0.x + q0.x) + (r0.x + s0.x);
        a0.y = (p0.y + q0.y) + (r0.y + s0.y);
        a0.z = (p0.z + q0.z) + (r0.z + s0.z);
        a0.w = (p0.w + q0.w) + (r0.w + s0.w);
        a1.x = (p1.x + q1.x) + (r1.x + s1.x);
        a1.y = (p1.y + q1.y) + (r1.y + s1.y);
        a1.z = (p1.z + q1.z) + (r1.z + s1.z);
        a1.w = (p1.w + q1.w) + (r1.w + s1.w);
    };

    loadX(0, x0, x1);
    w0 = *(const float4*)&W[(size_t)wk * HID + col0 + wc];
    w1 = *(const float4*)&W[(size_t)wk * HID + col0 + wc + 4];

    for (int kt = 0; kt < HID; kt += 16) {
        __syncthreads();
        sX[lc + 0][lr] = x0.x; sX[lc + 1][lr] = x0.y; sX[lc + 2][lr] = x0.z; sX[lc + 3][lr] = x0.w;
        sX[lc + 4][lr] = x1.x; sX[lc + 5][lr] = x1.y; sX[lc + 6][lr] = x1.z; sX[lc + 7][lr] = x1.w;
        *(float4*)&sW[wk][wc] = w0;
        *(float4*)&sW[wk][wc + 4] = w1;
        __syncthreads();

        int kn = kt + 16;
        if (kn < HID) {
            loadX(kn, x0, x1);
            w0 = *(const float4*)&W[(size_t)(kn + wk) * HID + col0 + wc];
            w1 = *(const float4*)&W[(size_t)(kn + wk) * HID + col0 + wc + 4];
        }

#pragma unroll
        for (int kk = 0; kk < 16; kk++) {
            float4 a0 = *(float4*)&sX[kk][ty * 4];
            float4 a1 = *(float4*)&sX[kk][64 + ty * 4];
            ulonglong2 bA = *(ulonglong2*)&sW[kk][tx * 4];
            ulonglong2 bB = *(ulonglong2*)&sW[kk][64 + tx * 4];
            u64t b2[4] = {bA.x, bA.y, bB.x, bB.y};
            float a[8] = {a0.x, a0.y, a0.z, a0.w, a1.x, a1.y, a1.z, a1.w};
#pragma unroll
            for (int i = 0; i < 8; i++) {
                u64t a2 = pk2(a[i], a[i]);
#pragma unroll
                for (int p = 0; p < 4; p++)
                    fma2(acc2[i][p], a2, b2[p]);
            }
        }
    }

    float4 bv0 = *(const float4*)&bias[col0 + tx * 4];
    float4 bv1 = *(const float4*)&bias[col0 + 64 + tx * 4];
#pragma unroll
    for (int i = 0; i < 8; i++) {
        int rr = (i < 4) ? (ty * 4 + i) : (64 + ty * 4 + (i - 4));
        size_t base = (size_t)(row0 + rr) * HID;
        float2 c0 = up2(acc2[i][0]), c1 = up2(acc2[i][1]);
        float2 c2 = up2(acc2[i][2]), c3 = up2(acc2[i][3]);
        float4 o0, o1;
        o0.x = c0.x + bv0.x; o0.y = c0.y + bv0.y;
        o0.z = c1.x + bv0.z; o0.w = c1.y + bv0.w;
        o1.x = c2.x + bv1.x; o1.y = c2.y + bv1.y;
        o1.z = c3.x + bv1.z; o1.w = c3.y + bv1.w;
        *(float4*)&Y[base + col0 + tx * 4] = o0;
        *(float4*)&Y[base + col0 + 64 + tx * 4] = o1;
    }
}

// =====================================================================
// Host launcher
// =====================================================================
extern "C" void kernel_launch(void* const* d_in, const int* in_sizes, int n_in,
                              void* d_out, int out_size) {
    const float* q = (const float*)d_in[0];
    const float* k = (const float*)d_in[1];
    const float* v = (const float*)d_in[2];
    const float* attn_bias = (const float*)d_in[3];
    const int* attn_mask = (const int*)d_in[4];
    const float* Wq = (const float*)d_in[5];
    const float* bq = (const float*)d_in[6];
    const float* Wk = (const float*)d_in[7];
    const float* bk = (const float*)d_in[8];
    const float* Wv = (const float*)d_in[9];
    const float* bv = (const float*)d_in[10];
    const float* Wo = (const float*)d_in[11];
    const float* bo = (const float*)d_in[12];

    float* out = (float*)d_out;
    float* scores = out + (size_t)OUT_ELEMS;

    float *qh, *kh, *vh, *ctx0, *ctx1, *ctx2, *ctx3, *part, *inv;
    cudaGetSymbolAddress((void**)&qh, g_qh);
    cudaGetSymbolAddress((void**)&kh, g_kh);
    cudaGetSymbolAddress((void**)&vh, g_vh);
    cudaGetSymbolAddress((void**)&ctx0, g_ctx0);
    cudaGetSymbolAddress((void**)&ctx1, g_ctx1);
    cudaGetSymbolAddress((void**)&ctx2, g_ctx2);
    cudaGetSymbolAddress((void**)&ctx3, g_ctx3);
    cudaGetSymbolAddress((void**)&part, g_part);
    cudaGetSymbolAddress((void**)&inv, g_inv);

    dim3 qg(HID / 128, NROWS / 128, 3); // (4, 32, 3)
    qkv_proj_kernel<<<qg, 256>>>(q, k, v, Wq, Wk, Wv, bq, bk, bv, qh, kh, vh);

    const int lsmem = (64 * 132 + 64 * 68) * (int)sizeof(float); // 51200
    cudaFuncSetAttribute(logits_kernel, cudaFuncAttributeMaxDynamicSharedMemorySize, lsmem);
    dim3 lg(SS / 64, SS / 128, NBH); // (32,16,16)
    logits_kernel<<<lg, 256, lsmem>>>(qh, kh, attn_bias, attn_mask, scores, part);

    reduce_kernel<<<(NBH * SS) / 256, 256>>>(part, inv);

    dim3 vg(SS / 128, NBH, 4); // (16,16,4)
    pv_kernel<<<vg, 256>>>(scores, vh, inv, ctx0, ctx1, ctx2, ctx3);

    dim3 pg(HID / 128, NROWS / 128); // (4, 32)
    out_proj_kernel<<<pg, 256>>>(ctx0, ctx1, ctx2, ctx3, Wo, bo, out);
}

// round 16
// speedup vs baseline: 1.0991x; 1.0280x over previous
#include <cuda_runtime.h>
#include <cuda_bf16.h>
#include <cstdint>
#include <cstddef>

// Problem constants
#define BB 2
#define SS 2048
#define NH 8
#define DD 64
#define HID 512
#define NROWS (BB * SS)           // 4096
#define OUT_ELEMS (BB * SS * HID) // 2097152
#define NBH (BB * NH)             // 16
#define NKT (SS / 128)            // 16 k-tiles per row

typedef unsigned long long u64t;

// ---------------- scratch (device globals; no allocation allowed) ----------------
__device__ float g_qh[NROWS * HID];
__device__ float g_kh[NROWS * HID];
__device__ float g_vh[NROWS * HID];
__device__ float g_ctx0[NROWS * HID];
__device__ float g_ctx1[NROWS * HID];
__device__ float g_ctx2[NROWS * HID];
__device__ float g_ctx3[NROWS * HID];
__device__ float g_part[NBH * SS * NKT]; // per (row, ktile): tile sum of exp(logit)
__device__ float g_inv[NBH * SS];        // per row: 1 / sum exp

// ---------------- packed f32x2 helpers (sm_100+ base PTX feature) ----------------
__device__ __forceinline__ u64t pk2(float x, float y) {
    u64t r;
    asm("mov.b64 %0, {%1, %2};" : "=l"(r) : "f"(x), "f"(y));
    return r;
}
__device__ __forceinline__ void fma2(u64t& d, u64t a, u64t b) {
    asm("fma.rn.f32x2 %0, %1, %2, %0;" : "+l"(d) : "l"(a), "l"(b));
}
__device__ __forceinline__ float2 up2(u64t v) {
    float2 r;
    asm("mov.b64 {%0, %1}, %2;" : "=f"(r.x), "=f"(r.y) : "l"(v));
    return r;
}

__device__ __forceinline__ uint32_t smem_u32(const void* p) {
    uint32_t a;
    asm("{ .reg .u64 t; cvta.to.shared.u64 t, %1; cvt.u32.u64 %0, t; }" : "=r"(a) : "l"(p));
    return a;
}
#define CP_ASYNC16(saddr, gptr) \
    asm volatile("cp.async.cg.shared.global [%0], [%1], 16;" :: "r"(saddr), "l"(gptr))
#define CP_COMMIT() asm volatile("cp.async.commit_group;" ::: "memory")
#define CP_WAIT0() asm volatile("cp.async.wait_group 0;" ::: "memory")

// Fast exp on the FMA pipe. exp(x) = 2^(x*log2e). Max rel err ~1.3e-6.
// Clamped at 2^-126 so -1e9 inputs underflow to ~0. Logits are bounded
// (|logit| <~ 15) so no overflow without max-shifting.
__device__ __forceinline__ float fexp(float x) {
    float t = x * 1.4426950408889634f;
    t = fmaxf(t, -126.0f);
    float nf = floorf(t);
    float f = t - nf;
    float p = 1.5252733e-5f;
    p = fmaf(p, f, 1.5403530e-4f);
    p = fmaf(p, f, 1.3333558e-3f);
    p = fmaf(p, f, 9.6181291e-3f);
    p = fmaf(p, f, 5.5504109e-2f);
    p = fmaf(p, f, 2.4022651e-1f);
    p = fmaf(p, f, 6.9314718e-1f);
    p = fmaf(p, f, 1.0f);
    float s = __int_as_float(((int)nf + 127) << 23);
    return s * p;
}

// =====================================================================
// Kernel 1: fused QKV projection, register-prefetch pipelined, f32x2 FMA.
// =====================================================================
__global__ __launch_bounds__(256) void qkv_proj_kernel(
    const float* __restrict__ q, const float* __restrict__ k, const float* __restrict__ v,
    const float* __restrict__ Wq, const float* __restrict__ Wk, const float* __restrict__ Wv,
    const float* __restrict__ bq, const float* __restrict__ bk, const float* __restrict__ bv,
    float* __restrict__ qh, float* __restrict__ kh, float* __restrict__ vh) {
    __shared__ __align__(16) float sX[16][132];
    __shared__ __align__(16) float sW[16][132];

    const int z = blockIdx.z;
    const float* X = (z == 0) ? q : (z == 1) ? k : v;
    const float* W = (z == 0) ? Wq : (z == 1) ? Wk : Wv;
    const float* bias = (z == 0) ? bq : (z == 1) ? bk : bv;
    float* Y = (z == 0) ? qh : (z == 1) ? kh : vh;

    const int t = threadIdx.x;
    const int tx = t & 15, ty = t >> 4;
    const int row0 = blockIdx.y * 128;
    const int col0 = blockIdx.x * 128;

    const int lr = t >> 1;
    const int lc = (t & 1) * 8;
    const int wk = t >> 4;
    const int wc = (t & 15) * 8;

    u64t acc2[8][4] = {};
    float4 x0, x1, w0, w1;

    {
        size_t xo = (size_t)(row0 + lr) * HID + lc;
        x0 = *(const float4*)&X[xo];
        x1 = *(const float4*)&X[xo + 4];
        w0 = *(const float4*)&W[(size_t)wk * HID + col0 + wc];
        w1 = *(const float4*)&W[(size_t)wk * HID + col0 + wc + 4];
    }

    for (int kt = 0; kt < HID; kt += 16) {
        __syncthreads();
        sX[lc + 0][lr] = x0.x; sX[lc + 1][lr] = x0.y; sX[lc + 2][lr] = x0.z; sX[lc + 3][lr] = x0.w;
        sX[lc + 4][lr] = x1.x; sX[lc + 5][lr] = x1.y; sX[lc + 6][lr] = x1.z; sX[lc + 7][lr] = x1.w;
        *(float4*)&sW[wk][wc] = w0;
        *(float4*)&sW[wk][wc + 4] = w1;
        __syncthreads();

        int kn = kt + 16;
        if (kn < HID) { // issue next tile's loads under the FMA loop
            size_t xo = (size_t)(row0 + lr) * HID + kn + lc;
            x0 = *(const float4*)&X[xo];
            x1 = *(const float4*)&X[xo + 4];
            w0 = *(const float4*)&W[(size_t)(kn + wk) * HID + col0 + wc];
            w1 = *(const float4*)&W[(size_t)(kn + wk) * HID + col0 + wc + 4];
        }

#pragma unroll
        for (int kk = 0; kk < 16; kk++) {
            float4 a0 = *(float4*)&sX[kk][ty * 4];
            float4 a1 = *(float4*)&sX[kk][64 + ty * 4];
            ulonglong2 bA = *(ulonglong2*)&sW[kk][tx * 4];
            ulonglong2 bB = *(ulonglong2*)&sW[kk][64 + tx * 4];
            u64t b2[4] = {bA.x, bA.y, bB.x, bB.y};
            float a[8] = {a0.x, a0.y, a0.z, a0.w, a1.x, a1.y, a1.z, a1.w};
#pragma unroll
            for (int i = 0; i < 8; i++) {
                u64t a2 = pk2(a[i], a[i]);
#pragma unroll
                for (int p = 0; p < 4; p++)
                    fma2(acc2[i][p], a2, b2[p]);
            }
        }
    }

    float4 bv0 = *(const float4*)&bias[col0 + tx * 4];
    float4 bv1 = *(const float4*)&bias[col0 + 64 + tx * 4];
#pragma unroll
    for (int i = 0; i < 8; i++) {
        int rr = (i < 4) ? (ty * 4 + i) : (64 + ty * 4 + (i - 4));
        size_t base = (size_t)(row0 + rr) * HID;
        float2 c0 = up2(acc2[i][0]), c1 = up2(acc2[i][1]);
        float2 c2 = up2(acc2[i][2]), c3 = up2(acc2[i][3]);
        float4 o0, o1;
        o0.x = c0.x + bv0.x; o0.y = c0.y + bv0.y;
        o0.z = c1.x + bv0.z; o0.w = c1.y + bv0.w;
        o1.x = c2.x + bv1.x; o1.y = c2.y + bv1.y;
        o1.z = c3.x + bv1.z; o1.w = c3.y + bv1.w;
        *(float4*)&Y[base + col0 + tx * 4] = o0;
        *(float4*)&Y[base + col0 + 64 + tx * 4] = o1;
    }
}

// =====================================================================
// Kernel 2: fused logits + exp + tile row-sum, f32x2 mainloop.
// Bias prefetched into smem via cp.async: chunk 0 (q-rows 0..63) hides
// under the GEMM; chunk 1 issued after the first-half epilogue.
// =====================================================================
__global__ __launch_bounds__(256) void logits_kernel(const float* __restrict__ qh,
                                                     const float* __restrict__ kh,
                                                     const float* __restrict__ bias,
                                                     const int* __restrict__ mask,
                                                     float* __restrict__ L,
                                                     float* __restrict__ part) {
    extern __shared__ float sm[];
    float* sQ = sm;                 // [64][132] transposed [d][row]
    float* sK = sm + 64 * 132;      // [64][132] transposed [d][col]
    float* sB = sm + 2 * 64 * 132;  // [64][128] bias chunk (32 KB)

    const int t = threadIdx.x;
    const int tx = t & 15, ty = t >> 4;
    const int kt = blockIdx.x * 128;
    const int ktile = blockIdx.x;
    const int qt = blockIdx.y * 128;
    const int bh = blockIdx.z;
    const int b = bh >> 3, h = bh & 7;

    const float* Qb = qh + (size_t)b * SS * HID + h * DD;
    const float* Kb = kh + (size_t)b * SS * HID + h * DD;
    const uint32_t sB_u32 = smem_u32(sB);

    // stage Q,K transposed
#pragma unroll
    for (int i = 0; i < 8; i++) {
        int f4i = t + 256 * i;
        int r = f4i >> 4;
        int d4 = (f4i & 15) * 4;
        float4 xq = *(const float4*)&Qb[(size_t)(qt + r) * HID + d4];
        sQ[(d4 + 0) * 132 + r] = xq.x; sQ[(d4 + 1) * 132 + r] = xq.y;
        sQ[(d4 + 2) * 132 + r] = xq.z; sQ[(d4 + 3) * 132 + r] = xq.w;
        float4 xk = *(const float4*)&Kb[(size_t)(kt + r) * HID + d4];
        sK[(d4 + 0) * 132 + r] = xk.x; sK[(d4 + 1) * 132 + r] = xk.y;
        sK[(d4 + 2) * 132 + r] = xk.z; sK[(d4 + 3) * 132 + r] = xk.w;
    }

    // issue bias chunk 0 (q-rows qt+0..63): latency hides under the GEMM
#pragma unroll
    for (int i = 0; i < 8; i++) {
        int idx = t + 256 * i;       // 0..2047
        int r = idx >> 5;            // 0..63
        int c4 = (idx & 31) * 4;     // 0..124
        const float* src = &bias[((size_t)bh * SS + qt + r) * SS + kt + c4];
        CP_ASYNC16(sB_u32 + (uint32_t)(r * 128 + c4) * 4u, src);
    }
    CP_COMMIT();
    __syncthreads();

    u64t acc2[8][4] = {}; // [row i][col pair p]
#pragma unroll
    for (int d = 0; d < 64; d++) {
        float4 a0 = *(float4*)&sQ[d * 132 + ty * 4];
        float4 a1 = *(float4*)&sQ[d * 132 + 64 + ty * 4];
        ulonglong2 bA = *(ulonglong2*)&sK[d * 132 + tx * 4];
        ulonglong2 bB = *(ulonglong2*)&sK[d * 132 + 64 + tx * 4];
        u64t b2[4] = {bA.x, bA.y, bB.x, bB.y};
        float a[8] = {a0.x, a0.y, a0.z, a0.w, a1.x, a1.y, a1.z, a1.w};
#pragma unroll
        for (int i = 0; i < 8; i++) {
            u64t a2 = pk2(a[i], a[i]);
#pragma unroll
            for (int p = 0; p < 4; p++)
                fma2(acc2[i][p], a2, b2[p]);
        }
    }

    CP_WAIT0();
    __syncthreads(); // chunk 0 visible to all

    const float scale = 0.125f;
    // ---- first half: i = 0..3 (rows qt+0..63, bias from sB) ----
#pragma unroll
    for (int i = 0; i < 4; i++) {
        int rr = ty * 4 + i;
        int qr = qt + rr;
        size_t boff = ((size_t)bh * SS + qr) * SS + kt;
        size_t moff = ((size_t)b * SS + qr) * SS + kt;
        float2 c0 = up2(acc2[i][0]), c1 = up2(acc2[i][1]);
        float2 c2 = up2(acc2[i][2]), c3 = up2(acc2[i][3]);
        float ac[8] = {c0.x, c0.y, c1.x, c1.y, c2.x, c2.y, c3.x, c3.y};
        float e[8]; float s = 0.f;
#pragma unroll
        for (int g = 0; g < 2; g++) {
            int c = g * 64 + tx * 4;
            float4 bv = *(float4*)&sB[rr * 128 + c];
            int4 mv = *(const int4*)&mask[moff + c];
            float v0 = mv.x ? -1e9f : fmaf(ac[4 * g + 0], scale, bv.x);
            float v1 = mv.y ? -1e9f : fmaf(ac[4 * g + 1], scale, bv.y);
            float v2 = mv.z ? -1e9f : fmaf(ac[4 * g + 2], scale, bv.z);
            float v3 = mv.w ? -1e9f : fmaf(ac[4 * g + 3], scale, bv.w);
            e[4 * g + 0] = fexp(v0); e[4 * g + 1] = fexp(v1);
            e[4 * g + 2] = fexp(v2); e[4 * g + 3] = fexp(v3);
            s += e[4 * g + 0] + e[4 * g + 1] + e[4 * g + 2] + e[4 * g + 3];
        }
#pragma unroll
        for (int off = 8; off >= 1; off >>= 1)
            s += __shfl_xor_sync(0xFFFFFFFFu, s, off);

        float4 o0 = {e[0], e[1], e[2], e[3]};
        float4 o1 = {e[4], e[5], e[6], e[7]};
        *(float4*)&L[boff + tx * 4] = o0;
        *(float4*)&L[boff + 64 + tx * 4] = o1;
        if (tx == 0)
            part[((size_t)bh * SS + qr) * NKT + ktile] = s;
    }

    __syncthreads(); // chunk 0 reads done
    // issue bias chunk 1 (q-rows qt+64..127)
#pragma unroll
    for (int i = 0; i < 8; i++) {
        int idx = t + 256 * i;
        int r = idx >> 5;            // 0..63
        int c4 = (idx & 31) * 4;
        const float* src = &bias[((size_t)bh * SS + qt + 64 + r) * SS + kt + c4];
        CP_ASYNC16(sB_u32 + (uint32_t)(r * 128 + c4) * 4u, src);
    }
    CP_COMMIT();
    CP_WAIT0();
    __syncthreads();

    // ---- second half: i = 4..7 (rows qt+64..127) ----
#pragma unroll
    for (int i = 4; i < 8; i++) {
        int rr = 64 + ty * 4 + (i - 4);
        int qr = qt + rr;
        size_t boff = ((size_t)bh * SS + qr) * SS + kt;
        size_t moff = ((size_t)b * SS + qr) * SS + kt;
        float2 c0 = up2(acc2[i][0]), c1 = up2(acc2[i][1]);
        float2 c2 = up2(acc2[i][2]), c3 = up2(acc2[i][3]);
        float ac[8] = {c0.x, c0.y, c1.x, c1.y, c2.x, c2.y, c3.x, c3.y};
        float e[8]; float s = 0.f;
#pragma unroll
        for (int g = 0; g < 2; g++) {
            int c = g * 64 + tx * 4;
            float4 bv = *(float4*)&sB[(rr - 64) * 128 + c];
            int4 mv = *(const int4*)&mask[moff + c];
            float v0 = mv.x ? -1e9f : fmaf(ac[4 * g + 0], scale, bv.x);
            float v1 = mv.y ? -1e9f : fmaf(ac[4 * g + 1], scale, bv.y);
            float v2 = mv.z ? -1e9f : fmaf(ac[4 * g + 2], scale, bv.z);
            float v3 = mv.w ? -1e9f : fmaf(ac[4 * g + 3], scale, bv.w);
            e[4 * g + 0] = fexp(v0); e[4 * g + 1] = fexp(v1);
            e[4 * g + 2] = fexp(v2); e[4 * g + 3] = fexp(v3);
            s += e[4 * g + 0] + e[4 * g + 1] + e[4 * g + 2] + e[4 * g + 3];
        }
#pragma unroll
        for (int off = 8; off >= 1; off >>= 1)
            s += __shfl_xor_sync(0xFFFFFFFFu, s, off);

        float4 o0 = {e[0], e[1], e[2], e[3]};
        float4 o1 = {e[4], e[5], e[6], e[7]};
        *(float4*)&L[boff + tx * 4] = o0;
        *(float4*)&L[boff + 64 + tx * 4] = o1;
        if (tx == 0)
            part[((size_t)bh * SS + qr) * NKT + ktile] = s;
    }
}

// =====================================================================
// Kernel 3: per-row reduce of tile sums -> inv_l
// =====================================================================
__global__ __launch_bounds__(256) void reduce_kernel(const float* __restrict__ part,
                                                     float* __restrict__ inv) {
    int row = blockIdx.x * 256 + threadIdx.x; // < NBH*SS
    float l = 0.f;
#pragma unroll
    for (int j = 0; j < NKT; j++)
        l += part[(size_t)row * NKT + j];
    inv[row] = 1.0f / l;
}

// =====================================================================
// Kernel 4: P = E * inv_l (in-place) and ctx_partial = P @ V.
// BM=128, BN=64, BK=32, 256 threads, split-K=4, reg-prefetch, f32x2 FMA.
// (R13 version, unchanged.)
// =====================================================================
__global__ __launch_bounds__(256) void pv_kernel(float* __restrict__ P,
                                                 const float* __restrict__ vh,
                                                 const float* __restrict__ inv,
                                                 float* __restrict__ ctx0,
                                                 float* __restrict__ ctx1,
                                                 float* __restrict__ ctx2,
                                                 float* __restrict__ ctx3) {
    __shared__ __align__(16) float sE[32 * 132]; // [k][row]
    __shared__ __align__(16) float sV[32 * 68];  // [k][col]
    __shared__ __align__(16) float sInv[128];

    const int t = threadIdx.x;
    const int tx = t & 15, ty = t >> 4;
    const int qt = blockIdx.x * 128;
    const int bh = blockIdx.y;
    const int ks = blockIdx.z;
    const int b = bh >> 3, h = bh & 7;

    float* dst = (ks == 0) ? ctx0 : (ks == 1) ? ctx1 : (ks == 2) ? ctx2 : ctx3;

    if (t < 128) sInv[t] = inv[(size_t)bh * SS + qt + t];

    u64t acc2[4][4] = {}; // [row pair p][col j]
    float* Pb = P + ((size_t)bh * SS + qt) * SS;
    const float* Vb = vh + (size_t)b * SS * HID + h * DD;

    const int er = t >> 3;          // base E row 0..31 (i adds 32*i)
    const int ec = (t & 7) * 4;     // E col-in-tile 0..28
    const int vr = t >> 4;          // base V k-row 0..15 (i adds 16*i)
    const int vc = (t & 15) * 4;    // V col 0..60

    const int kbeg = ks * (SS / 4);
    const int kend = kbeg + SS / 4;

    float4 eR[4], vR[2];
#pragma unroll
    for (int i = 0; i < 4; i++)
        eR[i] = *(const float4*)&Pb[(size_t)(er + 32 * i) * SS + kbeg + ec];
#pragma unroll
    for (int i = 0; i < 2; i++)
        vR[i] = *(const float4*)&Vb[(size_t)(kbeg + vr + 16 * i) * HID + vc];

    __syncthreads(); // sInv visible

    for (int k0 = kbeg; k0 < kend; k0 += 32) {
#pragma unroll
        for (int i = 0; i < 4; i++) {
            int r = er + 32 * i;
            float f = sInv[r];
            float4 pvv;
            pvv.x = eR[i].x * f; pvv.y = eR[i].y * f;
            pvv.z = eR[i].z * f; pvv.w = eR[i].w * f;
            *(float4*)&Pb[(size_t)r * SS + k0 + ec] = pvv;
            sE[(ec + 0) * 132 + r] = pvv.x;
            sE[(ec + 1) * 132 + r] = pvv.y;
            sE[(ec + 2) * 132 + r] = pvv.z;
            sE[(ec + 3) * 132 + r] = pvv.w;
        }
#pragma unroll
        for (int i = 0; i < 2; i++)
            *(float4*)&sV[(vr + 16 * i) * 68 + vc] = vR[i];
        __syncthreads();

        int kn = k0 + 32;
        if (kn < kend) {
#pragma unroll
            for (int i = 0; i < 4; i++)
                eR[i] = *(const float4*)&Pb[(size_t)(er + 32 * i) * SS + kn + ec];
#pragma unroll
            for (int i = 0; i < 2; i++)
                vR[i] = *(const float4*)&Vb[(size_t)(kn + vr + 16 * i) * HID + vc];
        }

#pragma unroll
        for (int kk = 0; kk < 32; kk++) {
            ulonglong2 aA = *(ulonglong2*)&sE[kk * 132 + ty * 4];
            ulonglong2 aB = *(ulonglong2*)&sE[kk * 132 + 64 + ty * 4];
            float4 bv = *(float4*)&sV[kk * 68 + tx * 4];
            u64t a2[4] = {aA.x, aA.y, aB.x, aB.y};
            u64t b2[4] = {pk2(bv.x, bv.x), pk2(bv.y, bv.y),
                          pk2(bv.z, bv.z), pk2(bv.w, bv.w)};
#pragma unroll
            for (int p = 0; p < 4; p++)
#pragma unroll
                for (int j = 0; j < 4; j++)
                    fma2(acc2[p][j], a2[p], b2[j]);
        }
        __syncthreads();
    }

#pragma unroll
    for (int p = 0; p < 4; p++) {
        float2 c0 = up2(acc2[p][0]), c1 = up2(acc2[p][1]);
        float2 c2 = up2(acc2[p][2]), c3 = up2(acc2[p][3]);
        int r0 = (p < 2) ? (ty * 4 + 2 * p) : (64 + ty * 4 + 2 * (p - 2));
        size_t base0 = (size_t)(b * SS + qt + r0) * HID + h * DD + tx * 4;
        size_t base1 = (size_t)(b * SS + qt + r0 + 1) * HID + h * DD + tx * 4;
        float4 oLo = {c0.x, c1.x, c2.x, c3.x};
        float4 oHi = {c0.y, c1.y, c2.y, c3.y};
        *(float4*)&dst[base0] = oLo;
        *(float4*)&dst[base1] = oHi;
    }
}

// =====================================================================
// Kernel 5: output projection  Y = (X0+X1+X2+X3) @ W + b, f32x2 FMA.
// (R13 version, unchanged.)
// =====================================================================
__global__ __launch_bounds__(256) void out_proj_kernel(const float* __restrict__ X0,
                                                       const float* __restrict__ X1,
                                                       const float* __restrict__ X2,
                                                       const float* __restrict__ X3,
                                                       const float* __restrict__ W,
                                                       const float* __restrict__ bias,
                                                       float* __restrict__ Y) {
    __shared__ __align__(16) float sX[16][132];
    __shared__ __align__(16) float sW[16][132];

    const int t = threadIdx.x;
    const int tx = t & 15, ty = t >> 4;
    const int row0 = blockIdx.y * 128;
    const int col0 = blockIdx.x * 128;

    const int lr = t >> 1;
    const int lc = (t & 1) * 8;
    const int wk = t >> 4;
    const int wc = (t & 15) * 8;

    u64t acc2[8][4] = {};
    float4 x0, x1, w0, w1;

    auto loadX = [&](int kt, float4& a0, float4& a1) {
        size_t xo = (size_t)(row0 + lr) * HID + kt + lc;
        float4 p0 = *(const float4*)&X0[xo];
        float4 p1 = *(const float4*)&X0[xo + 4];
        float4 q0 = *(const float4*)&X1[xo];
        float4 q1 = *(const float4*)&X1[xo + 4];
        float4 r0 = *(const float4*)&X2[xo];
        float4 r1 = *(const float4*)&X2[xo + 4];
        float4 s0 = *(const float4*)&X3[xo];
        float4 s1 = *(const float4*)&X3[xo + 4];
        a0.x = (p0.x + q0.x) + (r0.x + s0.x);
        a0.y = (p0.y + q0.y) + (r0.y + s0.y);
        a0.z = (p0.z + q0.z) + (r0.z + s0.z);
        a0.w = (p0.w + q0.w) + (r0.w + s0.w);
        a1.x = (p1.x + q1.x) + (r1.x + s1.x);
        a1.y = (p1.y + q1.y) + (r1.y + s1.y);
        a1.z = (p1.z + q1.z) + (r1.z + s1.z);
        a1.w = (p1.w + q1.w) + (r1.w + s1.w);
    };

    loadX(0, x0, x1);
    w0 = *(const float4*)&W[(size_t)wk * HID + col0 + wc];
    w1 = *(const float4*)&W[(size_t)wk * HID + col0 + wc + 4];

    for (int kt = 0; kt < HID; kt += 16) {
        __syncthreads();
        sX[lc + 0][lr] = x0.x; sX[lc + 1][lr] = x0.y; sX[lc + 2][lr] = x0.z; sX[lc + 3][lr] = x0.w;
        sX[lc + 4][lr] = x1.x; sX[lc + 5][lr] = x1.y; sX[lc + 6][lr] = x1.z; sX[lc + 7][lr] = x1.w;
        *(float4*)&sW[wk][wc] = w0;
        *(float4*)&sW[wk][wc + 4] = w1;
        __syncthreads();

        int kn = kt + 16;
        if (kn < HID) {
            loadX(kn, x0, x1);
            w0 = *(const float4*)&W[(size_t)(kn + wk) * HID + col0 + wc];
            w1 = *(const float4*)&W[(size_t)(kn + wk) * HID + col0 + wc + 4];
        }

#pragma unroll
        for (int kk = 0; kk < 16; kk++) {
            float4 a0 = *(float4*)&sX[kk][ty * 4];
            float4 a1 = *(float4*)&sX[kk][64 + ty * 4];
            ulonglong2 bA = *(ulonglong2*)&sW[kk][tx * 4];
            ulonglong2 bB = *(ulonglong2*)&sW[kk][64 + tx * 4];
            u64t b2[4] = {bA.x, bA.y, bB.x, bB.y};
            float a[8] = {a0.x, a0.y, a0.z, a0.w, a1.x, a1.y, a1.z, a1.w};
#pragma unroll
            for (int i = 0; i < 8; i++) {
                u64t a2 = pk2(a[i], a[i]);
#pragma unroll
                for (int p = 0; p < 4; p++)
                    fma2(acc2[i][p], a2, b2[p]);
            }
        }
    }

    float4 bv0 = *(const float4*)&bias[col0 + tx * 4];
    float4 bv1 = *(const float4*)&bias[col0 + 64 + tx * 4];
#pragma unroll
    for (int i = 0; i < 8; i++) {
        int rr = (i < 4) ? (ty * 4 + i) : (64 + ty * 4 + (i - 4));
        size_t base = (size_t)(row0 + rr) * HID;
        float2 c0 = up2(acc2[i][0]), c1 = up2(acc2[i][1]);
        float2 c2 = up2(acc2[i][2]), c3 = up2(acc2[i][3]);
        float4 o0, o1;
        o0.x = c0.x + bv0.x; o0.y = c0.y + bv0.y;
        o0.z = c1.x + bv0.z; o0.w = c1.y + bv0.w;
        o1.x = c2.x + bv1.x; o1.y = c2.y + bv1.y;
        o1.z = c3.x + bv1.z; o1.w = c3.y + bv1.w;
        *(float4*)&Y[base + col0 + tx * 4] = o0;
        *(float4*)&Y[base + col0 + 64 + tx * 4] = o1;
    }
}

// =====================================================================
// Host launcher
// =====================================================================
extern "C" void kernel_launch(void* const* d_in, const int* in_sizes, int n_in,
                              void* d_out, int out_size) {
    const float* q = (const float*)d_in[0];
    const float* k = (const float*)d_in[1];
    const float* v = (const float*)d_in[2];
    const float* attn_bias = (const float*)d_in[3];
    const int* attn_mask = (const int*)d_in[4];
    const float* Wq = (const float*)d_in[5];
    const float* bq = (const float*)d_in[6];
    const float* Wk = (const float*)d_in[7];
    const float* bk = (const float*)d_in[8];
    const float* Wv = (const float*)d_in[9];
    const float* bv = (const float*)d_in[10];
    const float* Wo = (const float*)d_in[11];
    const float* bo = (const float*)d_in[12];

    float* out = (float*)d_out;
    float* scores = out + (size_t)OUT_ELEMS;

    float *qh, *kh, *vh, *ctx0, *ctx1, *ctx2, *ctx3, *part, *inv;
    cudaGetSymbolAddress((void**)&qh, g_qh);
    cudaGetSymbolAddress((void**)&kh, g_kh);
    cudaGetSymbolAddress((void**)&vh, g_vh);
    cudaGetSymbolAddress((void**)&ctx0, g_ctx0);
    cudaGetSymbolAddress((void**)&ctx1, g_ctx1);
    cudaGetSymbolAddress((void**)&ctx2, g_ctx2);
    cudaGetSymbolAddress((void**)&ctx3, g_ctx3);
    cudaGetSymbolAddress((void**)&part, g_part);
    cudaGetSymbolAddress((void**)&inv, g_inv);

    dim3 qg(HID / 128, NROWS / 128, 3); // (4, 32, 3)
    qkv_proj_kernel<<<qg, 256>>>(q, k, v, Wq, Wk, Wv, bq, bk, bv, qh, kh, vh);

    const int lsmem = (2 * 64 * 132 + 64 * 128) * (int)sizeof(float); // 100352
    cudaFuncSetAttribute(logits_kernel, cudaFuncAttributeMaxDynamicSharedMemorySize, lsmem);
    dim3 lg(SS / 128, SS / 128, NBH); // (16,16,16)
    logits_kernel<<<lg, 256, lsmem>>>(qh, kh, attn_bias, attn_mask, scores, part);

    reduce_kernel<<<(NBH * SS) / 256, 256>>>(part, inv);

    dim3 vg(SS / 128, NBH, 4); // (16,16,4)
    pv_kernel<<<vg, 256>>>(scores, vh, inv, ctx0, ctx1, ctx2, ctx3);

    dim3 pg(HID / 128, NROWS / 128); // (4, 32)
    out_proj_kernel<<<pg, 256>>>(ctx0, ctx1, ctx2, ctx3, Wo, bo, out);
}